// round 9
// baseline (speedup 1.0000x reference)
#include <cuda_runtime.h>
#include <cstdint>

#define B_EV 4
#define NP 8192
#define MP 2048
#define KNN 64
#define NC (B_EV * MP)
#define R2F 0.04f
#define BIGF 1e10f
#define CAP 512

#define XLEN (NC * 128)
#define POS_OFF XLEN
#define BATCH_OFF (XLEN + NC * 3)

typedef unsigned long long ull;

__device__ float g_centers[NC * 3];
__device__ int   g_nbr[NC * KNN];
__device__ int   g_cnt[NC];
__device__ float g_U[B_EV * NP * 64];

__device__ __forceinline__ float dist2(float dx, float dy, float dz) {
    return __fadd_rn(__fadd_rn(__fmul_rn(dx, dx), __fmul_rn(dy, dy)),
                     __fmul_rn(dz, dz));
}

#define FMA2(acc, a, b) \
    asm("fma.rn.f32x2 %0, %1, %2, %0;" : "+l"(acc) : "l"(a), "l"(b))
#define ADD2(dst, a, b) \
    asm("add.rn.f32x2 %0, %1, %2;" : "=l"(dst) : "l"(a), "l"(b))
#define MUL2(dst, a, b) \
    asm("mul.rn.f32x2 %0, %1, %2;" : "=l"(dst) : "l"(a), "l"(b))

__device__ __forceinline__ ull pack2(float v) {
    ull r; asm("mov.b64 %0, {%1, %1};" : "=l"(r) : "r"(__float_as_uint(v)));
    return r;
}
__device__ __forceinline__ ull packf2(float lo, float hi) {
    ull r; asm("mov.b64 %0, {%1, %2};" : "=l"(r)
        : "r"(__float_as_uint(lo)), "r"(__float_as_uint(hi)));
    return r;
}
__device__ __forceinline__ float2 unpack2(ull p) {
    unsigned lo, hi; asm("mov.b64 {%0, %1}, %2;" : "=r"(lo), "=r"(hi) : "l"(p));
    return make_float2(__uint_as_float(lo), __uint_as_float(hi));
}

// ============================================================================
// Kernel 1: FPS. 1024 threads x 8 pts, Morton counting-sort, per-thread bbox
// prune (sound, 1e-6 deflated), one barrier/iter, key-based selection
// (d_bits<<32 | ~orig_idx) -> max d, ties to lowest original index
// (== jnp.argmax). All d-values follow the exact reference rounding chain.
// ============================================================================
#define FT 1024

__global__ __launch_bounds__(FT) void fps_kernel(const float* __restrict__ pos) {
    const int e = blockIdx.x;
    const float* pe = pos + (size_t)e * NP * 3;
    const int tid = threadIdx.x;
    const int lane = tid & 31;
    const int wid = tid >> 5;   // 32 warps

    extern __shared__ float sm[];
    float* sx = sm;
    float* sy = sx + NP;
    float* sz = sy + NP;
    int*   sidx = (int*)(sz + NP);
    __shared__ int s_cnt[64];
    __shared__ ull s_key[2][32];

    if (tid < 64) s_cnt[tid] = 0;
    __syncthreads();

    float ox[8], oy[8], oz[8];
    int cel[8];
#pragma unroll
    for (int t = 0; t < 8; t++) {
        const int j = tid + t * FT;
        ox[t] = pe[3 * j]; oy[t] = pe[3 * j + 1]; oz[t] = pe[3 * j + 2];
        int ix = (int)(ox[t] * 4.f); ix = ix < 3 ? ix : 3;
        int iy = (int)(oy[t] * 4.f); iy = iy < 3 ? iy : 3;
        int iz = (int)(oz[t] * 4.f); iz = iz < 3 ? iz : 3;
        cel[t] = ((ix >> 1) << 5) | ((iy >> 1) << 4) | ((iz >> 1) << 3) |
                 ((ix & 1) << 2) | ((iy & 1) << 1) | (iz & 1);
        atomicAdd(&s_cnt[cel[t]], 1);
    }
    __syncthreads();
    if (tid == 0) {
        int run = 0;
        for (int c2 = 0; c2 < 64; c2++) { const int v = s_cnt[c2]; s_cnt[c2] = run; run += v; }
    }
    __syncthreads();
#pragma unroll
    for (int t = 0; t < 8; t++) {
        const int p = atomicAdd(&s_cnt[cel[t]], 1);
        sx[p] = ox[t]; sy[p] = oy[t]; sz[p] = oz[t]; sidx[p] = tid + t * FT;
    }
    __syncthreads();

    ull pxp[4], pyp[4], pzp[4];
    int io[8];
    float d[8];
    float tbnx = 2.f, tbny = 2.f, tbnz = 2.f, tbxx = -1.f, tbxy = -1.f, tbxz = -1.f;
    const int base = tid * 8;
#pragma unroll
    for (int j = 0; j < 4; j++) {
        const float ax = sx[base + 2 * j], bx = sx[base + 2 * j + 1];
        const float ay = sy[base + 2 * j], by = sy[base + 2 * j + 1];
        const float az = sz[base + 2 * j], bz = sz[base + 2 * j + 1];
        pxp[j] = packf2(ax, bx); pyp[j] = packf2(ay, by); pzp[j] = packf2(az, bz);
        io[2 * j] = sidx[base + 2 * j]; io[2 * j + 1] = sidx[base + 2 * j + 1];
        tbnx = fminf(tbnx, fminf(ax, bx)); tbxx = fmaxf(tbxx, fmaxf(ax, bx));
        tbny = fminf(tbny, fminf(ay, by)); tbxy = fmaxf(tbxy, fmaxf(ay, by));
        tbnz = fminf(tbnz, fminf(az, bz)); tbxz = fmaxf(tbxz, fmaxf(az, bz));
    }
    __syncthreads();   // sorted reads done -> repurpose buffers

    // orig-indexed position copy for O(LDS) next-center lookup
#pragma unroll
    for (int t = 0; t < 8; t++) {
        const int j = tid + t * FT;
        sx[j] = ox[t]; sy[j] = oy[t]; sz[j] = oz[t];
    }

    const float c0x = pe[0], c0y = pe[1], c0z = pe[2];
    {
        const ull ncx = pack2(-c0x), ncy = pack2(-c0y), ncz = pack2(-c0z);
#pragma unroll
        for (int j = 0; j < 4; j++) {
            ull dx, dy, dz, qx, qy, qz, s1, s2;
            ADD2(dx, pxp[j], ncx); ADD2(dy, pyp[j], ncy); ADD2(dz, pzp[j], ncz);
            MUL2(qx, dx, dx); MUL2(qy, dy, dy); MUL2(qz, dz, dz);
            ADD2(s1, qx, qy); ADD2(s2, s1, qz);
            const float2 f = unpack2(s2);
            d[2 * j] = f.x; d[2 * j + 1] = f.y;
        }
    }
    ull mykey;
    float tdmax;
    {
        float mm = d[0];
#pragma unroll
        for (int t = 1; t < 8; t++) mm = fmaxf(mm, d[t]);
        tdmax = mm;
        const unsigned wb = __reduce_max_sync(0xffffffffu, __float_as_uint(mm));
        unsigned cl = 0;
#pragma unroll
        for (int t = 0; t < 8; t++)
            if (__float_as_uint(d[t]) == wb) cl = max(cl, ~(unsigned)io[t]);
        const unsigned wl = __reduce_max_sync(0xffffffffu, cl);
        mykey = ((ull)wb << 32) | wl;
    }
    if (lane == 0) s_key[0][wid] = mykey;
    if (tid == 0) {
        g_centers[(e * MP) * 3 + 0] = c0x;
        g_centers[(e * MP) * 3 + 1] = c0y;
        g_centers[(e * MP) * 3 + 2] = c0z;
    }

    for (int i = 1; i < MP; i++) {
        __syncthreads();
        const ull kk = s_key[(i - 1) & 1][lane];
        const unsigned hi = (unsigned)(kk >> 32);
        const unsigned lo = (unsigned)kk;
        const unsigned mhi = __reduce_max_sync(0xffffffffu, hi);
        const unsigned mlo = __reduce_max_sync(0xffffffffu, (hi == mhi) ? lo : 0u);
        const int nxt = (int)(~mlo);

        const float nx = sx[nxt], ny = sy[nxt], nz = sz[nxt];
        if (tid == 0) {
            g_centers[(e * MP + i) * 3 + 0] = nx;
            g_centers[(e * MP + i) * 3 + 1] = ny;
            g_centers[(e * MP + i) * 3 + 2] = nz;
        }

        const float lbx = fmaxf(fmaxf(tbnx - nx, nx - tbxx), 0.f);
        const float lby = fmaxf(fmaxf(tbny - ny, ny - tbxy), 0.f);
        const float lbz = fmaxf(fmaxf(tbnz - nz, nz - tbxz), 0.f);
        const float lb2 = ((lbx * lbx + lby * lby) + lbz * lbz) * 0.999999f;
        const bool needs = (lb2 < tdmax);

        if (__any_sync(0xffffffffu, needs)) {
            const ull ncx = pack2(-nx), ncy = pack2(-ny), ncz = pack2(-nz);
            float mm = 0.f;
#pragma unroll
            for (int j = 0; j < 4; j++) {
                ull dx, dy, dz, qx, qy, qz, s1, s2;
                ADD2(dx, pxp[j], ncx); ADD2(dy, pyp[j], ncy); ADD2(dz, pzp[j], ncz);
                MUL2(qx, dx, dx); MUL2(qy, dy, dy); MUL2(qz, dz, dz);
                ADD2(s1, qx, qy); ADD2(s2, s1, qz);
                const float2 f = unpack2(s2);
                d[2 * j]     = fminf(d[2 * j], f.x);
                d[2 * j + 1] = fminf(d[2 * j + 1], f.y);
                mm = fmaxf(mm, fmaxf(d[2 * j], d[2 * j + 1]));
            }
            tdmax = mm;
            const unsigned wb = __reduce_max_sync(0xffffffffu, __float_as_uint(mm));
            unsigned cl = 0;
#pragma unroll
            for (int t = 0; t < 8; t++)
                if (__float_as_uint(d[t]) == wb) cl = max(cl, ~(unsigned)io[t]);
            const unsigned wl = __reduce_max_sync(0xffffffffu, cl);
            mykey = ((ull)wb << 32) | wl;
        }
        if (lane == 0) s_key[i & 1][wid] = mykey;
    }
}

// ============================================================================
// Kernel 2: ball query + top-K (unchanged, known good)
// ============================================================================
__global__ __launch_bounds__(256) void bq_kernel(const float* __restrict__ pos) {
    __shared__ float s_d2[8][CAP];
    __shared__ int   s_idx[8][CAP];

    const int w = threadIdx.x >> 5;
    const int lane = threadIdx.x & 31;
    const int c = blockIdx.x * 8 + w;
    const int e = c >> 11;
    const float* pe = pos + (size_t)e * NP * 3;

    const float cx = g_centers[c * 3 + 0];
    const float cy = g_centers[c * 3 + 1];
    const float cz = g_centers[c * 3 + 2];

    int cnt = 0;
    const unsigned lmask = (1u << lane) - 1u;
    for (int j = lane; j < NP; j += 32) {
        const float d2v = dist2(pe[3 * j] - cx, pe[3 * j + 1] - cy, pe[3 * j + 2] - cz);
        const bool inr = (d2v <= R2F);
        const unsigned mball = __ballot_sync(0xffffffffu, inr);
        if (inr) {
            const int slot = cnt + __popc(mball & lmask);
            if (slot < CAP) { s_d2[w][slot] = d2v; s_idx[w][slot] = j; }
        }
        cnt += __popc(mball);
    }
    const int C = (cnt < CAP) ? cnt : CAP;

    if (C <= KNN) {
        for (int k = lane; k < KNN; k += 32)
            g_nbr[c * KNN + k] = (k < C) ? s_idx[w][k] : 0;
        if (lane == 0) g_cnt[c] = C;
    } else {
        for (int s = 0; s < KNN; s++) {
            ull best = ~0ull;
            for (int t = lane; t < C; t += 32) {
                const ull key = ((ull)__float_as_uint(s_d2[w][t]) << 32) | (unsigned)t;
                best = (key < best) ? key : best;
            }
#pragma unroll
            for (int o = 16; o > 0; o >>= 1) {
                const ull other = __shfl_down_sync(0xffffffffu, best, o);
                best = (other < best) ? other : best;
            }
            best = __shfl_sync(0xffffffffu, best, 0);
            const int slot = (int)(unsigned)best;
            if (lane == 0) {
                g_nbr[c * KNN + s] = s_idx[w][slot];
                s_d2[w][slot] = BIGF;
            }
            __syncwarp();
        }
        if (lane == 0) g_cnt[c] = KNN;
    }
}

// ============================================================================
// Kernel 0b: U = b1 + x @ W1[0:32]  (unchanged, known good)
// ============================================================================
__global__ __launch_bounds__(256) void upre_kernel(
    const float* __restrict__ x, const float* __restrict__ W1,
    const float* __restrict__ b1)
{
    __shared__ float sW[32 * 64];
    __shared__ float sb[64];
    const int tid = threadIdx.x;
    for (int i = tid; i < 2048; i += 256) sW[i] = W1[i];
    if (tid < 64) sb[tid] = b1[tid];
    __syncthreads();

    const int row = blockIdx.x * 256 + tid;
    float inv[32];
    const float4* xr = (const float4*)(x + (size_t)row * 32);
#pragma unroll
    for (int q = 0; q < 8; q++) {
        const float4 v = xr[q];
        inv[4 * q] = v.x; inv[4 * q + 1] = v.y; inv[4 * q + 2] = v.z; inv[4 * q + 3] = v.w;
    }
    float4* ur = (float4*)(g_U + (size_t)row * 64);
#pragma unroll
    for (int h = 0; h < 2; h++) {
        ull acc[16];
#pragma unroll
        for (int k = 0; k < 8; k++) {
            const ulonglong2 bb = *(const ulonglong2*)(sb + h * 32 + 4 * k);
            acc[2 * k] = bb.x; acc[2 * k + 1] = bb.y;
        }
#pragma unroll
        for (int i = 0; i < 32; i++) {
            const ull a = pack2(inv[i]);
#pragma unroll
            for (int k = 0; k < 8; k++) {
                const ulonglong2 wv = *(const ulonglong2*)(sW + i * 64 + h * 32 + 4 * k);
                FMA2(acc[2 * k], a, wv.x);
                FMA2(acc[2 * k + 1], a, wv.y);
            }
        }
#pragma unroll
        for (int k = 0; k < 8; k++) {
            const float2 v0 = unpack2(acc[2 * k]);
            const float2 v1 = unpack2(acc[2 * k + 1]);
            ur[h * 8 + k] = make_float4(v0.x, v0.y, v1.x, v1.y);
        }
    }
}

// ============================================================================
// Kernel 3: gather + MLP + max-pool (R5/R7 known-good: regs=168, no spill)
// ============================================================================
__global__ __launch_bounds__(128, 3) void mlp_kernel(
    const float* __restrict__ pos,
    const float* __restrict__ W1,
    const float* __restrict__ W2, const float* __restrict__ b2,
    const float* __restrict__ W3, const float* __restrict__ b3,
    float* __restrict__ out)
{
    extern __shared__ float smem[];
    float* sW1p = smem;            // 192
    float* sW2 = sW1p + 192;       // 4096
    float* sW3 = sW2 + 4096;       // 8192
    float* sb2 = sW3 + 8192;       // 64
    float* sb3 = sb2 + 64;         // 128
    int*   sOut = (int*)(sb3 + 128);

    const int tid = threadIdx.x;
    for (int i = tid; i < 192; i += 128) sW1p[i] = W1[2048 + i];
    for (int i = tid; i < 4096; i += 128) sW2[i] = W2[i];
    for (int i = tid; i < 8192; i += 128) sW3[i] = W3[i];
    if (tid < 64) sb2[tid] = b2[tid];
    sb3[tid] = b3[tid];
    sOut[tid] = 0;
    sOut[tid + 128] = 0;
    __syncthreads();

    const int cl = tid >> 6;
    const int n  = tid & 63;
    const int lane = tid & 31;
    const int c  = blockIdx.x * 2 + cl;
    const int e  = c >> 11;
    const bool active = (n < g_cnt[c]);
    int* sOutC = sOut + cl * 128;

    const int idx = g_nbr[c * KNN + n];
    const int row = e * NP + idx;

    float rel[3];
    rel[0] = pos[row * 3 + 0] - g_centers[c * 3 + 0];
    rel[1] = pos[row * 3 + 1] - g_centers[c * 3 + 1];
    rel[2] = pos[row * 3 + 2] - g_centers[c * 3 + 2];

    float h1[64];
    const float4* ur = (const float4*)(g_U + (size_t)row * 64);
#pragma unroll
    for (int h = 0; h < 2; h++) {
        ull acc[16];
#pragma unroll
        for (int q = 0; q < 8; q++) {
            const float4 u = ur[h * 8 + q];
            acc[2 * q]     = packf2(u.x, u.y);
            acc[2 * q + 1] = packf2(u.z, u.w);
        }
#pragma unroll
        for (int i = 0; i < 3; i++) {
            const ull a = pack2(rel[i]);
#pragma unroll
            for (int k = 0; k < 8; k++) {
                const ulonglong2 wv = *(const ulonglong2*)(sW1p + i * 64 + h * 32 + 4 * k);
                FMA2(acc[2 * k], a, wv.x);
                FMA2(acc[2 * k + 1], a, wv.y);
            }
        }
#pragma unroll
        for (int k = 0; k < 16; k++) {
            const float2 v = unpack2(acc[k]);
            h1[h * 32 + 2 * k]     = fmaxf(v.x, 0.f);
            h1[h * 32 + 2 * k + 1] = fmaxf(v.y, 0.f);
        }
    }

    float h2[64];
#pragma unroll
    for (int q = 0; q < 4; q++) {
        ull acc[8];
#pragma unroll
        for (int k = 0; k < 4; k++) {
            const ulonglong2 bb = *(const ulonglong2*)(sb2 + q * 16 + 4 * k);
            acc[2 * k] = bb.x; acc[2 * k + 1] = bb.y;
        }
#pragma unroll
        for (int i = 0; i < 64; i++) {
            const ull a = pack2(h1[i]);
#pragma unroll
            for (int k = 0; k < 4; k++) {
                const ulonglong2 wv = *(const ulonglong2*)(sW2 + i * 64 + q * 16 + 4 * k);
                FMA2(acc[2 * k], a, wv.x);
                FMA2(acc[2 * k + 1], a, wv.y);
            }
        }
#pragma unroll
        for (int k = 0; k < 8; k++) {
            const float2 v = unpack2(acc[k]);
            h2[q * 16 + 2 * k]     = fmaxf(v.x, 0.f);
            h2[q * 16 + 2 * k + 1] = fmaxf(v.y, 0.f);
        }
    }

#pragma unroll
    for (int qd = 0; qd < 4; qd++) {
        ull acc[16];
#pragma unroll
        for (int k = 0; k < 8; k++) {
            const ulonglong2 bb = *(const ulonglong2*)(sb3 + qd * 32 + 4 * k);
            acc[2 * k] = bb.x; acc[2 * k + 1] = bb.y;
        }
#pragma unroll
        for (int i = 0; i < 64; i++) {
            const ull a = pack2(h2[i]);
#pragma unroll
            for (int k = 0; k < 8; k++) {
                const ulonglong2 wv = *(const ulonglong2*)(sW3 + i * 128 + qd * 32 + 4 * k);
                FMA2(acc[2 * k], a, wv.x);
                FMA2(acc[2 * k + 1], a, wv.y);
            }
        }
#pragma unroll
        for (int k = 0; k < 16; k++) {
            const float2 v = unpack2(acc[k]);
            float v0 = active ? fmaxf(v.x, 0.f) : 0.f;
            float v1 = active ? fmaxf(v.y, 0.f) : 0.f;
#pragma unroll
            for (int o = 16; o >= 4; o >>= 1) {
                v0 = fmaxf(v0, __shfl_xor_sync(0xffffffffu, v0, o));
                v1 = fmaxf(v1, __shfl_xor_sync(0xffffffffu, v1, o));
            }
            if (lane < 4) {
                atomicMax(sOutC + qd * 32 + 2 * k,     __float_as_int(v0));
                atomicMax(sOutC + qd * 32 + 2 * k + 1, __float_as_int(v1));
            }
        }
    }
    __syncthreads();

    {
        int i = tid;
        int cc = blockIdx.x * 2 + (i >> 7);
        out[(size_t)cc * 128 + (i & 127)] = __int_as_float(sOut[i]);
        i = tid + 128;
        cc = blockIdx.x * 2 + (i >> 7);
        out[(size_t)cc * 128 + (i & 127)] = __int_as_float(sOut[i]);
    }
    if (tid < 6) {
        const int cc = blockIdx.x * 2 + (tid / 3);
        out[POS_OFF + (size_t)cc * 3 + (tid % 3)] = g_centers[cc * 3 + (tid % 3)];
    }
    if (tid < 2) {
        const int cc = blockIdx.x * 2 + tid;
        out[BATCH_OFF + cc] = (float)(cc >> 11);
    }
}

// ============================================================================
extern "C" void kernel_launch(void* const* d_in, const int* in_sizes, int n_in,
                              void* d_out, int out_size) {
    const float* x   = (const float*)d_in[0];
    const float* pos = (const float*)d_in[1];
    const float* W1 = (const float*)d_in[3];
    const float* b1 = (const float*)d_in[4];
    const float* W2 = (const float*)d_in[5];
    const float* b2 = (const float*)d_in[6];
    const float* W3 = (const float*)d_in[7];
    const float* b3 = (const float*)d_in[8];
    float* out = (float*)d_out;

    const int fps_smem = 4 * NP * 4;
    cudaFuncSetAttribute(fps_kernel, cudaFuncAttributeMaxDynamicSharedMemorySize,
                         fps_smem);
    fps_kernel<<<B_EV, FT, fps_smem>>>(pos);

    upre_kernel<<<(B_EV * NP) / 256, 256>>>(x, W1, b1);
    bq_kernel<<<NC / 8, 256>>>(pos);

    const int mlp_smem = (192 + 4096 + 8192 + 64 + 128 + 256) * 4;
    cudaFuncSetAttribute(mlp_kernel, cudaFuncAttributeMaxDynamicSharedMemorySize,
                         mlp_smem);
    mlp_kernel<<<NC / 2, 128, mlp_smem>>>(pos, W1, W2, b2, W3, b3, out);
}

// round 11
// speedup vs baseline: 1.0745x; 1.0745x over previous
#include <cuda_runtime.h>
#include <cstdint>

#define B_EV 4
#define NP 8192
#define MP 2048
#define KNN 64
#define NC (B_EV * MP)
#define R2F 0.04f
#define BIGF 1e10f
#define CAP 512

#define XLEN (NC * 128)
#define POS_OFF XLEN
#define BATCH_OFF (XLEN + NC * 3)

typedef unsigned long long ull;

__device__ float g_centers[NC * 3];
__device__ int   g_nbr[NC * KNN];
__device__ int   g_cnt[NC];
__device__ float g_U[B_EV * NP * 64];

__device__ __forceinline__ float dist2(float dx, float dy, float dz) {
    return __fadd_rn(__fadd_rn(__fmul_rn(dx, dx), __fmul_rn(dy, dy)),
                     __fmul_rn(dz, dz));
}

#define FMA2(acc, a, b) \
    asm("fma.rn.f32x2 %0, %1, %2, %0;" : "+l"(acc) : "l"(a), "l"(b))
#define ADD2(dst, a, b) \
    asm("add.rn.f32x2 %0, %1, %2;" : "=l"(dst) : "l"(a), "l"(b))
#define MUL2(dst, a, b) \
    asm("mul.rn.f32x2 %0, %1, %2;" : "=l"(dst) : "l"(a), "l"(b))

__device__ __forceinline__ ull pack2(float v) {
    ull r; asm("mov.b64 %0, {%1, %1};" : "=l"(r) : "r"(__float_as_uint(v)));
    return r;
}
__device__ __forceinline__ ull packf2(float lo, float hi) {
    ull r; asm("mov.b64 %0, {%1, %2};" : "=l"(r)
        : "r"(__float_as_uint(lo)), "r"(__float_as_uint(hi)));
    return r;
}
__device__ __forceinline__ float2 unpack2(ull p) {
    unsigned lo, hi; asm("mov.b64 {%0, %1}, %2;" : "=r"(lo), "=r"(hi) : "l"(p));
    return make_float2(__uint_as_float(lo), __uint_as_float(hi));
}

// ============================================================================
// Kernel 1: FPS (R7-proven: 512 threads x 16 pts). Morton counting-sort,
// per-thread bbox prune (sound, 1e-6 deflated), one barrier/iter, key-based
// selection (d_bits<<32 | ~orig_idx) -> max d, ties to lowest original index
// (== jnp.argmax). Exact reference rounding chain. Micro-opts vs R7: tie-scan
// gated on (local max == warp max).
// ============================================================================
#define FT 512

__global__ __launch_bounds__(FT) void fps_kernel(const float* __restrict__ pos) {
    const int e = blockIdx.x;
    const float* pe = pos + (size_t)e * NP * 3;
    const int tid = threadIdx.x;
    const int lane = tid & 31;
    const int wid = tid >> 5;

    extern __shared__ float sm[];
    float* sx = sm;
    float* sy = sx + NP;
    float* sz = sy + NP;
    int*   sidx = (int*)(sz + NP);
    __shared__ int s_cnt[64];
    __shared__ ull s_key[2][16];

    if (tid < 64) s_cnt[tid] = 0;
    __syncthreads();

    float ox[16], oy[16], oz[16];
    int cel[16];
#pragma unroll
    for (int t = 0; t < 16; t++) {
        const int j = tid + t * FT;
        ox[t] = pe[3 * j]; oy[t] = pe[3 * j + 1]; oz[t] = pe[3 * j + 2];
        int ix = (int)(ox[t] * 4.f); ix = ix < 3 ? ix : 3;
        int iy = (int)(oy[t] * 4.f); iy = iy < 3 ? iy : 3;
        int iz = (int)(oz[t] * 4.f); iz = iz < 3 ? iz : 3;
        cel[t] = ((ix >> 1) << 5) | ((iy >> 1) << 4) | ((iz >> 1) << 3) |
                 ((ix & 1) << 2) | ((iy & 1) << 1) | (iz & 1);
        atomicAdd(&s_cnt[cel[t]], 1);
    }
    __syncthreads();
    if (tid == 0) {
        int run = 0;
        for (int c2 = 0; c2 < 64; c2++) { const int v = s_cnt[c2]; s_cnt[c2] = run; run += v; }
    }
    __syncthreads();
#pragma unroll
    for (int t = 0; t < 16; t++) {
        const int p = atomicAdd(&s_cnt[cel[t]], 1);
        sx[p] = ox[t]; sy[p] = oy[t]; sz[p] = oz[t]; sidx[p] = tid + t * FT;
    }
    __syncthreads();

    ull pxp[8], pyp[8], pzp[8];
    int io[16];
    float d[16];
    float tbnx = 2.f, tbny = 2.f, tbnz = 2.f, tbxx = -1.f, tbxy = -1.f, tbxz = -1.f;
    const int base = tid * 16;
#pragma unroll
    for (int j = 0; j < 8; j++) {
        const float ax = sx[base + 2 * j], bx = sx[base + 2 * j + 1];
        const float ay = sy[base + 2 * j], by = sy[base + 2 * j + 1];
        const float az = sz[base + 2 * j], bz = sz[base + 2 * j + 1];
        pxp[j] = packf2(ax, bx); pyp[j] = packf2(ay, by); pzp[j] = packf2(az, bz);
        io[2 * j] = sidx[base + 2 * j]; io[2 * j + 1] = sidx[base + 2 * j + 1];
        tbnx = fminf(tbnx, fminf(ax, bx)); tbxx = fmaxf(tbxx, fmaxf(ax, bx));
        tbny = fminf(tbny, fminf(ay, by)); tbxy = fmaxf(tbxy, fmaxf(ay, by));
        tbnz = fminf(tbnz, fminf(az, bz)); tbxz = fmaxf(tbxz, fmaxf(az, bz));
    }
    __syncthreads();   // sorted reads done -> repurpose buffers

    // orig-indexed position copy for O(LDS) next-center lookup
#pragma unroll
    for (int t = 0; t < 16; t++) {
        const int j = tid + t * FT;
        sx[j] = ox[t]; sy[j] = oy[t]; sz[j] = oz[t];
    }

    const float c0x = pe[0], c0y = pe[1], c0z = pe[2];
    {
        const ull ncx = pack2(-c0x), ncy = pack2(-c0y), ncz = pack2(-c0z);
#pragma unroll
        for (int j = 0; j < 8; j++) {
            ull dx, dy, dz, qx, qy, qz, s1, s2;
            ADD2(dx, pxp[j], ncx); ADD2(dy, pyp[j], ncy); ADD2(dz, pzp[j], ncz);
            MUL2(qx, dx, dx); MUL2(qy, dy, dy); MUL2(qz, dz, dz);
            ADD2(s1, qx, qy); ADD2(s2, s1, qz);
            const float2 f = unpack2(s2);
            d[2 * j] = f.x; d[2 * j + 1] = f.y;
        }
    }
    ull mykey;
    float tdmax;
    {
        float mm = d[0];
#pragma unroll
        for (int t = 1; t < 16; t++) mm = fmaxf(mm, d[t]);
        tdmax = mm;
        const unsigned wb = __reduce_max_sync(0xffffffffu, __float_as_uint(mm));
        unsigned cl = 0;
        if (__float_as_uint(mm) == wb) {
#pragma unroll
            for (int t = 0; t < 16; t++)
                if (__float_as_uint(d[t]) == wb) cl = max(cl, ~(unsigned)io[t]);
        }
        const unsigned wl = __reduce_max_sync(0xffffffffu, cl);
        mykey = ((ull)wb << 32) | wl;
    }
    if (lane == 0) s_key[0][wid] = mykey;
    if (tid == 0) {
        g_centers[(e * MP) * 3 + 0] = c0x;
        g_centers[(e * MP) * 3 + 1] = c0y;
        g_centers[(e * MP) * 3 + 2] = c0z;
    }

    for (int i = 1; i < MP; i++) {
        __syncthreads();
        const ull kk = s_key[(i - 1) & 1][lane & 15];
        const unsigned hi = (unsigned)(kk >> 32);
        const unsigned lo = (unsigned)kk;
        const unsigned mhi = __reduce_max_sync(0xffffffffu, hi);
        const unsigned mlo = __reduce_max_sync(0xffffffffu, (hi == mhi) ? lo : 0u);
        const int nxt = (int)(~mlo);

        const float nx = sx[nxt], ny = sy[nxt], nz = sz[nxt];
        if (tid == 0) {
            g_centers[(e * MP + i) * 3 + 0] = nx;
            g_centers[(e * MP + i) * 3 + 1] = ny;
            g_centers[(e * MP + i) * 3 + 2] = nz;
        }

        const float lbx = fmaxf(fmaxf(tbnx - nx, nx - tbxx), 0.f);
        const float lby = fmaxf(fmaxf(tbny - ny, ny - tbxy), 0.f);
        const float lbz = fmaxf(fmaxf(tbnz - nz, nz - tbxz), 0.f);
        const float lb2 = ((lbx * lbx + lby * lby) + lbz * lbz) * 0.999999f;
        const bool needs = (lb2 < tdmax);

        if (__any_sync(0xffffffffu, needs)) {
            const ull ncx = pack2(-nx), ncy = pack2(-ny), ncz = pack2(-nz);
            float mm = 0.f;
#pragma unroll
            for (int j = 0; j < 8; j++) {
                ull dx, dy, dz, qx, qy, qz, s1, s2;
                ADD2(dx, pxp[j], ncx); ADD2(dy, pyp[j], ncy); ADD2(dz, pzp[j], ncz);
                MUL2(qx, dx, dx); MUL2(qy, dy, dy); MUL2(qz, dz, dz);
                ADD2(s1, qx, qy); ADD2(s2, s1, qz);
                const float2 f = unpack2(s2);
                d[2 * j]     = fminf(d[2 * j], f.x);
                d[2 * j + 1] = fminf(d[2 * j + 1], f.y);
                mm = fmaxf(mm, fmaxf(d[2 * j], d[2 * j + 1]));
            }
            tdmax = mm;
            const unsigned wb = __reduce_max_sync(0xffffffffu, __float_as_uint(mm));
            unsigned cl = 0;
            if (__float_as_uint(mm) == wb) {
#pragma unroll
                for (int t = 0; t < 16; t++)
                    if (__float_as_uint(d[t]) == wb) cl = max(cl, ~(unsigned)io[t]);
            }
            const unsigned wl = __reduce_max_sync(0xffffffffu, cl);
            mykey = ((ull)wb << 32) | wl;
        }
        if (lane == 0) s_key[i & 1][wid] = mykey;
    }
}

// ============================================================================
// Kernel 2: ball query + top-K (unchanged, known good)
// ============================================================================
__global__ __launch_bounds__(256) void bq_kernel(const float* __restrict__ pos) {
    __shared__ float s_d2[8][CAP];
    __shared__ int   s_idx[8][CAP];

    const int w = threadIdx.x >> 5;
    const int lane = threadIdx.x & 31;
    const int c = blockIdx.x * 8 + w;
    const int e = c >> 11;
    const float* pe = pos + (size_t)e * NP * 3;

    const float cx = g_centers[c * 3 + 0];
    const float cy = g_centers[c * 3 + 1];
    const float cz = g_centers[c * 3 + 2];

    int cnt = 0;
    const unsigned lmask = (1u << lane) - 1u;
    for (int j = lane; j < NP; j += 32) {
        const float d2v = dist2(pe[3 * j] - cx, pe[3 * j + 1] - cy, pe[3 * j + 2] - cz);
        const bool inr = (d2v <= R2F);
        const unsigned mball = __ballot_sync(0xffffffffu, inr);
        if (inr) {
            const int slot = cnt + __popc(mball & lmask);
            if (slot < CAP) { s_d2[w][slot] = d2v; s_idx[w][slot] = j; }
        }
        cnt += __popc(mball);
    }
    const int C = (cnt < CAP) ? cnt : CAP;

    if (C <= KNN) {
        for (int k = lane; k < KNN; k += 32)
            g_nbr[c * KNN + k] = (k < C) ? s_idx[w][k] : 0;
        if (lane == 0) g_cnt[c] = C;
    } else {
        for (int s = 0; s < KNN; s++) {
            ull best = ~0ull;
            for (int t = lane; t < C; t += 32) {
                const ull key = ((ull)__float_as_uint(s_d2[w][t]) << 32) | (unsigned)t;
                best = (key < best) ? key : best;
            }
#pragma unroll
            for (int o = 16; o > 0; o >>= 1) {
                const ull other = __shfl_down_sync(0xffffffffu, best, o);
                best = (other < best) ? other : best;
            }
            best = __shfl_sync(0xffffffffu, best, 0);
            const int slot = (int)(unsigned)best;
            if (lane == 0) {
                g_nbr[c * KNN + s] = s_idx[w][slot];
                s_d2[w][slot] = BIGF;
            }
            __syncwarp();
        }
        if (lane == 0) g_cnt[c] = KNN;
    }
}

// ============================================================================
// Kernel 0b: U = b1 + x @ W1[0:32]  (unchanged, known good)
// ============================================================================
__global__ __launch_bounds__(256) void upre_kernel(
    const float* __restrict__ x, const float* __restrict__ W1,
    const float* __restrict__ b1)
{
    __shared__ float sW[32 * 64];
    __shared__ float sb[64];
    const int tid = threadIdx.x;
    for (int i = tid; i < 2048; i += 256) sW[i] = W1[i];
    if (tid < 64) sb[tid] = b1[tid];
    __syncthreads();

    const int row = blockIdx.x * 256 + tid;
    float inv[32];
    const float4* xr = (const float4*)(x + (size_t)row * 32);
#pragma unroll
    for (int q = 0; q < 8; q++) {
        const float4 v = xr[q];
        inv[4 * q] = v.x; inv[4 * q + 1] = v.y; inv[4 * q + 2] = v.z; inv[4 * q + 3] = v.w;
    }
    float4* ur = (float4*)(g_U + (size_t)row * 64);
#pragma unroll
    for (int h = 0; h < 2; h++) {
        ull acc[16];
#pragma unroll
        for (int k = 0; k < 8; k++) {
            const ulonglong2 bb = *(const ulonglong2*)(sb + h * 32 + 4 * k);
            acc[2 * k] = bb.x; acc[2 * k + 1] = bb.y;
        }
#pragma unroll
        for (int i = 0; i < 32; i++) {
            const ull a = pack2(inv[i]);
#pragma unroll
            for (int k = 0; k < 8; k++) {
                const ulonglong2 wv = *(const ulonglong2*)(sW + i * 64 + h * 32 + 4 * k);
                FMA2(acc[2 * k], a, wv.x);
                FMA2(acc[2 * k + 1], a, wv.y);
            }
        }
#pragma unroll
        for (int k = 0; k < 8; k++) {
            const float2 v0 = unpack2(acc[2 * k]);
            const float2 v1 = unpack2(acc[2 * k + 1]);
            ur[h * 8 + k] = make_float4(v0.x, v0.y, v1.x, v1.y);
        }
    }
}

// ============================================================================
// Kernel 3: gather + MLP + max-pool (R5/R7 known-good: regs=168, no spill)
// ============================================================================
__global__ __launch_bounds__(128, 3) void mlp_kernel(
    const float* __restrict__ pos,
    const float* __restrict__ W1,
    const float* __restrict__ W2, const float* __restrict__ b2,
    const float* __restrict__ W3, const float* __restrict__ b3,
    float* __restrict__ out)
{
    extern __shared__ float smem[];
    float* sW1p = smem;            // 192
    float* sW2 = sW1p + 192;       // 4096
    float* sW3 = sW2 + 4096;       // 8192
    float* sb2 = sW3 + 8192;       // 64
    float* sb3 = sb2 + 64;         // 128
    int*   sOut = (int*)(sb3 + 128);

    const int tid = threadIdx.x;
    for (int i = tid; i < 192; i += 128) sW1p[i] = W1[2048 + i];
    for (int i = tid; i < 4096; i += 128) sW2[i] = W2[i];
    for (int i = tid; i < 8192; i += 128) sW3[i] = W3[i];
    if (tid < 64) sb2[tid] = b2[tid];
    sb3[tid] = b3[tid];
    sOut[tid] = 0;
    sOut[tid + 128] = 0;
    __syncthreads();

    const int cl = tid >> 6;
    const int n  = tid & 63;
    const int lane = tid & 31;
    const int c  = blockIdx.x * 2 + cl;
    const int e  = c >> 11;
    const bool active = (n < g_cnt[c]);
    int* sOutC = sOut + cl * 128;

    const int idx = g_nbr[c * KNN + n];
    const int row = e * NP + idx;

    float rel[3];
    rel[0] = pos[row * 3 + 0] - g_centers[c * 3 + 0];
    rel[1] = pos[row * 3 + 1] - g_centers[c * 3 + 1];
    rel[2] = pos[row * 3 + 2] - g_centers[c * 3 + 2];

    float h1[64];
    const float4* ur = (const float4*)(g_U + (size_t)row * 64);
#pragma unroll
    for (int h = 0; h < 2; h++) {
        ull acc[16];
#pragma unroll
        for (int q = 0; q < 8; q++) {
            const float4 u = ur[h * 8 + q];
            acc[2 * q]     = packf2(u.x, u.y);
            acc[2 * q + 1] = packf2(u.z, u.w);
        }
#pragma unroll
        for (int i = 0; i < 3; i++) {
            const ull a = pack2(rel[i]);
#pragma unroll
            for (int k = 0; k < 8; k++) {
                const ulonglong2 wv = *(const ulonglong2*)(sW1p + i * 64 + h * 32 + 4 * k);
                FMA2(acc[2 * k], a, wv.x);
                FMA2(acc[2 * k + 1], a, wv.y);
            }
        }
#pragma unroll
        for (int k = 0; k < 16; k++) {
            const float2 v = unpack2(acc[k]);
            h1[h * 32 + 2 * k]     = fmaxf(v.x, 0.f);
            h1[h * 32 + 2 * k + 1] = fmaxf(v.y, 0.f);
        }
    }

    float h2[64];
#pragma unroll
    for (int q = 0; q < 4; q++) {
        ull acc[8];
#pragma unroll
        for (int k = 0; k < 4; k++) {
            const ulonglong2 bb = *(const ulonglong2*)(sb2 + q * 16 + 4 * k);
            acc[2 * k] = bb.x; acc[2 * k + 1] = bb.y;
        }
#pragma unroll
        for (int i = 0; i < 64; i++) {
            const ull a = pack2(h1[i]);
#pragma unroll
            for (int k = 0; k < 4; k++) {
                const ulonglong2 wv = *(const ulonglong2*)(sW2 + i * 64 + q * 16 + 4 * k);
                FMA2(acc[2 * k], a, wv.x);
                FMA2(acc[2 * k + 1], a, wv.y);
            }
        }
#pragma unroll
        for (int k = 0; k < 8; k++) {
            const float2 v = unpack2(acc[k]);
            h2[q * 16 + 2 * k]     = fmaxf(v.x, 0.f);
            h2[q * 16 + 2 * k + 1] = fmaxf(v.y, 0.f);
        }
    }

#pragma unroll
    for (int qd = 0; qd < 4; qd++) {
        ull acc[16];
#pragma unroll
        for (int k = 0; k < 8; k++) {
            const ulonglong2 bb = *(const ulonglong2*)(sb3 + qd * 32 + 4 * k);
            acc[2 * k] = bb.x; acc[2 * k + 1] = bb.y;
        }
#pragma unroll
        for (int i = 0; i < 64; i++) {
            const ull a = pack2(h2[i]);
#pragma unroll
            for (int k = 0; k < 8; k++) {
                const ulonglong2 wv = *(const ulonglong2*)(sW3 + i * 128 + qd * 32 + 4 * k);
                FMA2(acc[2 * k], a, wv.x);
                FMA2(acc[2 * k + 1], a, wv.y);
            }
        }
#pragma unroll
        for (int k = 0; k < 16; k++) {
            const float2 v = unpack2(acc[k]);
            float v0 = active ? fmaxf(v.x, 0.f) : 0.f;
            float v1 = active ? fmaxf(v.y, 0.f) : 0.f;
#pragma unroll
            for (int o = 16; o >= 4; o >>= 1) {
                v0 = fmaxf(v0, __shfl_xor_sync(0xffffffffu, v0, o));
                v1 = fmaxf(v1, __shfl_xor_sync(0xffffffffu, v1, o));
            }
            if (lane < 4) {
                atomicMax(sOutC + qd * 32 + 2 * k,     __float_as_int(v0));
                atomicMax(sOutC + qd * 32 + 2 * k + 1, __float_as_int(v1));
            }
        }
    }
    __syncthreads();

    {
        int i = tid;
        int cc = blockIdx.x * 2 + (i >> 7);
        out[(size_t)cc * 128 + (i & 127)] = __int_as_float(sOut[i]);
        i = tid + 128;
        cc = blockIdx.x * 2 + (i >> 7);
        out[(size_t)cc * 128 + (i & 127)] = __int_as_float(sOut[i]);
    }
    if (tid < 6) {
        const int cc = blockIdx.x * 2 + (tid / 3);
        out[POS_OFF + (size_t)cc * 3 + (tid % 3)] = g_centers[cc * 3 + (tid % 3)];
    }
    if (tid < 2) {
        const int cc = blockIdx.x * 2 + tid;
        out[BATCH_OFF + cc] = (float)(cc >> 11);
    }
}

// ============================================================================
extern "C" void kernel_launch(void* const* d_in, const int* in_sizes, int n_in,
                              void* d_out, int out_size) {
    const float* x   = (const float*)d_in[0];
    const float* pos = (const float*)d_in[1];
    const float* W1 = (const float*)d_in[3];
    const float* b1 = (const float*)d_in[4];
    const float* W2 = (const float*)d_in[5];
    const float* b2 = (const float*)d_in[6];
    const float* W3 = (const float*)d_in[7];
    const float* b3 = (const float*)d_in[8];
    float* out = (float*)d_out;

    const int fps_smem = 4 * NP * 4;   // 131072 B
    cudaFuncSetAttribute(fps_kernel, cudaFuncAttributeMaxDynamicSharedMemorySize,
                         fps_smem);
    fps_kernel<<<B_EV, FT, fps_smem>>>(pos);

    upre_kernel<<<(B_EV * NP) / 256, 256>>>(x, W1, b1);
    bq_kernel<<<NC / 8, 256>>>(pos);

    const int mlp_smem = (192 + 4096 + 8192 + 64 + 128 + 256) * 4;
    cudaFuncSetAttribute(mlp_kernel, cudaFuncAttributeMaxDynamicSharedMemorySize,
                         mlp_smem);
    mlp_kernel<<<NC / 2, 128, mlp_smem>>>(pos, W1, W2, b2, W3, b3, out);
}

// round 13
// speedup vs baseline: 1.0898x; 1.0143x over previous
#include <cuda_runtime.h>
#include <cstdint>

#define B_EV 4
#define NP 8192
#define MP 2048
#define KNN 64
#define NC (B_EV * MP)
#define R2F 0.04f
#define BIGF 1e10f
#define CAP 512

#define XLEN (NC * 128)
#define POS_OFF XLEN
#define BATCH_OFF (XLEN + NC * 3)

typedef unsigned long long ull;

__device__ float g_centers[NC * 3];
__device__ int   g_nbr[NC * KNN];
__device__ int   g_cnt[NC];
__device__ float g_U[B_EV * NP * 64];

// Warp-uniform weight copies on the CONSTANT port (separate pipe from L1TEX).
__constant__ ulonglong2 c_W2v[1024];   // W2 as ulonglong2[64][16]
__constant__ ulonglong2 c_W3v[2048];   // W3 as ulonglong2[64][32]

__device__ __forceinline__ float dist2(float dx, float dy, float dz) {
    return __fadd_rn(__fadd_rn(__fmul_rn(dx, dx), __fmul_rn(dy, dy)),
                     __fmul_rn(dz, dz));
}

#define FMA2(acc, a, b) \
    asm("fma.rn.f32x2 %0, %1, %2, %0;" : "+l"(acc) : "l"(a), "l"(b))
#define ADD2(dst, a, b) \
    asm("add.rn.f32x2 %0, %1, %2;" : "=l"(dst) : "l"(a), "l"(b))
#define MUL2(dst, a, b) \
    asm("mul.rn.f32x2 %0, %1, %2;" : "=l"(dst) : "l"(a), "l"(b))

__device__ __forceinline__ ull pack2(float v) {
    ull r; asm("mov.b64 %0, {%1, %1};" : "=l"(r) : "r"(__float_as_uint(v)));
    return r;
}
__device__ __forceinline__ ull packf2(float lo, float hi) {
    ull r; asm("mov.b64 %0, {%1, %2};" : "=l"(r)
        : "r"(__float_as_uint(lo)), "r"(__float_as_uint(hi)));
    return r;
}
__device__ __forceinline__ float2 unpack2(ull p) {
    unsigned lo, hi; asm("mov.b64 {%0, %1}, %2;" : "=r"(lo), "=r"(hi) : "l"(p));
    return make_float2(__uint_as_float(lo), __uint_as_float(hi));
}

// ============================================================================
// Kernel 1: FPS (exact R7-proven version: 512 threads x 16 pts).
// ============================================================================
#define FT 512

__global__ __launch_bounds__(FT) void fps_kernel(const float* __restrict__ pos) {
    const int e = blockIdx.x;
    const float* pe = pos + (size_t)e * NP * 3;
    const int tid = threadIdx.x;
    const int lane = tid & 31;
    const int wid = tid >> 5;

    extern __shared__ float sm[];
    float* sx = sm;
    float* sy = sx + NP;
    float* sz = sy + NP;
    int*   sidx = (int*)(sz + NP);
    __shared__ int s_cnt[64];
    __shared__ ull s_key[2][16];

    if (tid < 64) s_cnt[tid] = 0;
    __syncthreads();

    float ox[16], oy[16], oz[16];
    int cel[16];
#pragma unroll
    for (int t = 0; t < 16; t++) {
        const int j = tid + t * FT;
        ox[t] = pe[3 * j]; oy[t] = pe[3 * j + 1]; oz[t] = pe[3 * j + 2];
        int ix = (int)(ox[t] * 4.f); ix = ix < 3 ? ix : 3;
        int iy = (int)(oy[t] * 4.f); iy = iy < 3 ? iy : 3;
        int iz = (int)(oz[t] * 4.f); iz = iz < 3 ? iz : 3;
        cel[t] = ((ix >> 1) << 5) | ((iy >> 1) << 4) | ((iz >> 1) << 3) |
                 ((ix & 1) << 2) | ((iy & 1) << 1) | (iz & 1);
        atomicAdd(&s_cnt[cel[t]], 1);
    }
    __syncthreads();
    if (tid == 0) {
        int run = 0;
        for (int c2 = 0; c2 < 64; c2++) { const int v = s_cnt[c2]; s_cnt[c2] = run; run += v; }
    }
    __syncthreads();
#pragma unroll
    for (int t = 0; t < 16; t++) {
        const int p = atomicAdd(&s_cnt[cel[t]], 1);
        sx[p] = ox[t]; sy[p] = oy[t]; sz[p] = oz[t]; sidx[p] = tid + t * FT;
    }
    __syncthreads();

    ull pxp[8], pyp[8], pzp[8];
    int io[16];
    float d[16];
    float tbnx = 2.f, tbny = 2.f, tbnz = 2.f, tbxx = -1.f, tbxy = -1.f, tbxz = -1.f;
    const int base = tid * 16;
#pragma unroll
    for (int j = 0; j < 8; j++) {
        const float ax = sx[base + 2 * j], bx = sx[base + 2 * j + 1];
        const float ay = sy[base + 2 * j], by = sy[base + 2 * j + 1];
        const float az = sz[base + 2 * j], bz = sz[base + 2 * j + 1];
        pxp[j] = packf2(ax, bx); pyp[j] = packf2(ay, by); pzp[j] = packf2(az, bz);
        io[2 * j] = sidx[base + 2 * j]; io[2 * j + 1] = sidx[base + 2 * j + 1];
        tbnx = fminf(tbnx, fminf(ax, bx)); tbxx = fmaxf(tbxx, fmaxf(ax, bx));
        tbny = fminf(tbny, fminf(ay, by)); tbxy = fmaxf(tbxy, fmaxf(ay, by));
        tbnz = fminf(tbnz, fminf(az, bz)); tbxz = fmaxf(tbxz, fmaxf(az, bz));
    }
    __syncthreads();   // sorted reads done -> repurpose buffers

    // orig-indexed position copy for O(LDS) next-center lookup
#pragma unroll
    for (int t = 0; t < 16; t++) {
        const int j = tid + t * FT;
        sx[j] = ox[t]; sy[j] = oy[t]; sz[j] = oz[t];
    }

    const float c0x = pe[0], c0y = pe[1], c0z = pe[2];
    {
        const ull ncx = pack2(-c0x), ncy = pack2(-c0y), ncz = pack2(-c0z);
#pragma unroll
        for (int j = 0; j < 8; j++) {
            ull dx, dy, dz, qx, qy, qz, s1, s2;
            ADD2(dx, pxp[j], ncx); ADD2(dy, pyp[j], ncy); ADD2(dz, pzp[j], ncz);
            MUL2(qx, dx, dx); MUL2(qy, dy, dy); MUL2(qz, dz, dz);
            ADD2(s1, qx, qy); ADD2(s2, s1, qz);
            const float2 f = unpack2(s2);
            d[2 * j] = f.x; d[2 * j + 1] = f.y;
        }
    }
    ull mykey;
    float tdmax;
    {
        float mm = d[0];
#pragma unroll
        for (int t = 1; t < 16; t++) mm = fmaxf(mm, d[t]);
        tdmax = mm;
        const unsigned wb = __reduce_max_sync(0xffffffffu, __float_as_uint(mm));
        unsigned cl = 0;
#pragma unroll
        for (int t = 0; t < 16; t++)
            if (__float_as_uint(d[t]) == wb) cl = max(cl, ~(unsigned)io[t]);
        const unsigned wl = __reduce_max_sync(0xffffffffu, cl);
        mykey = ((ull)wb << 32) | wl;
    }
    if (lane == 0) s_key[0][wid] = mykey;
    if (tid == 0) {
        g_centers[(e * MP) * 3 + 0] = c0x;
        g_centers[(e * MP) * 3 + 1] = c0y;
        g_centers[(e * MP) * 3 + 2] = c0z;
    }

    for (int i = 1; i < MP; i++) {
        __syncthreads();
        const ull kk = s_key[(i - 1) & 1][lane & 15];
        const unsigned hi = (unsigned)(kk >> 32);
        const unsigned lo = (unsigned)kk;
        const unsigned mhi = __reduce_max_sync(0xffffffffu, hi);
        const unsigned mlo = __reduce_max_sync(0xffffffffu, (hi == mhi) ? lo : 0u);
        const int nxt = (int)(~mlo);

        const float nx = sx[nxt], ny = sy[nxt], nz = sz[nxt];
        if (tid == 0) {
            g_centers[(e * MP + i) * 3 + 0] = nx;
            g_centers[(e * MP + i) * 3 + 1] = ny;
            g_centers[(e * MP + i) * 3 + 2] = nz;
        }

        const float lbx = fmaxf(fmaxf(tbnx - nx, nx - tbxx), 0.f);
        const float lby = fmaxf(fmaxf(tbny - ny, ny - tbxy), 0.f);
        const float lbz = fmaxf(fmaxf(tbnz - nz, nz - tbxz), 0.f);
        const float lb2 = ((lbx * lbx + lby * lby) + lbz * lbz) * 0.999999f;
        const bool needs = (lb2 < tdmax);

        if (__any_sync(0xffffffffu, needs)) {
            const ull ncx = pack2(-nx), ncy = pack2(-ny), ncz = pack2(-nz);
            float mm = 0.f;
#pragma unroll
            for (int j = 0; j < 8; j++) {
                ull dx, dy, dz, qx, qy, qz, s1, s2;
                ADD2(dx, pxp[j], ncx); ADD2(dy, pyp[j], ncy); ADD2(dz, pzp[j], ncz);
                MUL2(qx, dx, dx); MUL2(qy, dy, dy); MUL2(qz, dz, dz);
                ADD2(s1, qx, qy); ADD2(s2, s1, qz);
                const float2 f = unpack2(s2);
                d[2 * j]     = fminf(d[2 * j], f.x);
                d[2 * j + 1] = fminf(d[2 * j + 1], f.y);
                mm = fmaxf(mm, fmaxf(d[2 * j], d[2 * j + 1]));
            }
            tdmax = mm;
            const unsigned wb = __reduce_max_sync(0xffffffffu, __float_as_uint(mm));
            unsigned cl = 0;
#pragma unroll
            for (int t = 0; t < 16; t++)
                if (__float_as_uint(d[t]) == wb) cl = max(cl, ~(unsigned)io[t]);
            const unsigned wl = __reduce_max_sync(0xffffffffu, cl);
            mykey = ((ull)wb << 32) | wl;
        }
        if (lane == 0) s_key[i & 1][wid] = mykey;
    }
}

// ============================================================================
// Kernel 2: ball query + top-K (unchanged, known good)
// ============================================================================
__global__ __launch_bounds__(256) void bq_kernel(const float* __restrict__ pos) {
    __shared__ float s_d2[8][CAP];
    __shared__ int   s_idx[8][CAP];

    const int w = threadIdx.x >> 5;
    const int lane = threadIdx.x & 31;
    const int c = blockIdx.x * 8 + w;
    const int e = c >> 11;
    const float* pe = pos + (size_t)e * NP * 3;

    const float cx = g_centers[c * 3 + 0];
    const float cy = g_centers[c * 3 + 1];
    const float cz = g_centers[c * 3 + 2];

    int cnt = 0;
    const unsigned lmask = (1u << lane) - 1u;
    for (int j = lane; j < NP; j += 32) {
        const float d2v = dist2(pe[3 * j] - cx, pe[3 * j + 1] - cy, pe[3 * j + 2] - cz);
        const bool inr = (d2v <= R2F);
        const unsigned mball = __ballot_sync(0xffffffffu, inr);
        if (inr) {
            const int slot = cnt + __popc(mball & lmask);
            if (slot < CAP) { s_d2[w][slot] = d2v; s_idx[w][slot] = j; }
        }
        cnt += __popc(mball);
    }
    const int C = (cnt < CAP) ? cnt : CAP;

    if (C <= KNN) {
        for (int k = lane; k < KNN; k += 32)
            g_nbr[c * KNN + k] = (k < C) ? s_idx[w][k] : 0;
        if (lane == 0) g_cnt[c] = C;
    } else {
        for (int s = 0; s < KNN; s++) {
            ull best = ~0ull;
            for (int t = lane; t < C; t += 32) {
                const ull key = ((ull)__float_as_uint(s_d2[w][t]) << 32) | (unsigned)t;
                best = (key < best) ? key : best;
            }
#pragma unroll
            for (int o = 16; o > 0; o >>= 1) {
                const ull other = __shfl_down_sync(0xffffffffu, best, o);
                best = (other < best) ? other : best;
            }
            best = __shfl_sync(0xffffffffu, best, 0);
            const int slot = (int)(unsigned)best;
            if (lane == 0) {
                g_nbr[c * KNN + s] = s_idx[w][slot];
                s_d2[w][slot] = BIGF;
            }
            __syncwarp();
        }
        if (lane == 0) g_cnt[c] = KNN;
    }
}

// ============================================================================
// Kernel 0b: U = b1 + x @ W1[0:32]  (unchanged, known good)
// ============================================================================
__global__ __launch_bounds__(256) void upre_kernel(
    const float* __restrict__ x, const float* __restrict__ W1,
    const float* __restrict__ b1)
{
    __shared__ float sW[32 * 64];
    __shared__ float sb[64];
    const int tid = threadIdx.x;
    for (int i = tid; i < 2048; i += 256) sW[i] = W1[i];
    if (tid < 64) sb[tid] = b1[tid];
    __syncthreads();

    const int row = blockIdx.x * 256 + tid;
    float inv[32];
    const float4* xr = (const float4*)(x + (size_t)row * 32);
#pragma unroll
    for (int q = 0; q < 8; q++) {
        const float4 v = xr[q];
        inv[4 * q] = v.x; inv[4 * q + 1] = v.y; inv[4 * q + 2] = v.z; inv[4 * q + 3] = v.w;
    }
    float4* ur = (float4*)(g_U + (size_t)row * 64);
#pragma unroll
    for (int h = 0; h < 2; h++) {
        ull acc[16];
#pragma unroll
        for (int k = 0; k < 8; k++) {
            const ulonglong2 bb = *(const ulonglong2*)(sb + h * 32 + 4 * k);
            acc[2 * k] = bb.x; acc[2 * k + 1] = bb.y;
        }
#pragma unroll
        for (int i = 0; i < 32; i++) {
            const ull a = pack2(inv[i]);
#pragma unroll
            for (int k = 0; k < 8; k++) {
                const ulonglong2 wv = *(const ulonglong2*)(sW + i * 64 + h * 32 + 4 * k);
                FMA2(acc[2 * k], a, wv.x);
                FMA2(acc[2 * k + 1], a, wv.y);
            }
        }
#pragma unroll
        for (int k = 0; k < 8; k++) {
            const float2 v0 = unpack2(acc[2 * k]);
            const float2 v1 = unpack2(acc[2 * k + 1]);
            ur[h * 8 + k] = make_float4(v0.x, v0.y, v1.x, v1.y);
        }
    }
}

// ============================================================================
// Kernel 3: gather + MLP + max-pool. R5-proven structure EXACTLY; the only
// change: half of W2/W3 reads come from __constant__ (separate constant port,
// warp-uniform addresses) instead of shared -> splits the 84%-busy L1TEX
// traffic across two pipes. Values and summation order identical.
// ============================================================================
__global__ __launch_bounds__(128, 3) void mlp_kernel(
    const float* __restrict__ pos,
    const float* __restrict__ W1,
    const float* __restrict__ W2, const float* __restrict__ b2,
    const float* __restrict__ W3, const float* __restrict__ b3,
    float* __restrict__ out)
{
    extern __shared__ float smem[];
    float* sW1p = smem;            // 192
    float* sW2 = sW1p + 192;       // 4096
    float* sW3 = sW2 + 4096;       // 8192
    float* sb2 = sW3 + 8192;       // 64
    float* sb3 = sb2 + 64;         // 128
    int*   sOut = (int*)(sb3 + 128);

    const int tid = threadIdx.x;
    for (int i = tid; i < 192; i += 128) sW1p[i] = W1[2048 + i];
    for (int i = tid; i < 4096; i += 128) sW2[i] = W2[i];
    for (int i = tid; i < 8192; i += 128) sW3[i] = W3[i];
    if (tid < 64) sb2[tid] = b2[tid];
    sb3[tid] = b3[tid];
    sOut[tid] = 0;
    sOut[tid + 128] = 0;
    __syncthreads();

    const int cl = tid >> 6;
    const int n  = tid & 63;
    const int lane = tid & 31;
    const int c  = blockIdx.x * 2 + cl;
    const int e  = c >> 11;
    const bool active = (n < g_cnt[c]);
    int* sOutC = sOut + cl * 128;

    const int idx = g_nbr[c * KNN + n];
    const int row = e * NP + idx;

    float rel[3];
    rel[0] = pos[row * 3 + 0] - g_centers[c * 3 + 0];
    rel[1] = pos[row * 3 + 1] - g_centers[c * 3 + 1];
    rel[2] = pos[row * 3 + 2] - g_centers[c * 3 + 2];

    float h1[64];
    const float4* ur = (const float4*)(g_U + (size_t)row * 64);
#pragma unroll
    for (int h = 0; h < 2; h++) {
        ull acc[16];
#pragma unroll
        for (int q = 0; q < 8; q++) {
            const float4 u = ur[h * 8 + q];
            acc[2 * q]     = packf2(u.x, u.y);
            acc[2 * q + 1] = packf2(u.z, u.w);
        }
#pragma unroll
        for (int i = 0; i < 3; i++) {
            const ull a = pack2(rel[i]);
#pragma unroll
            for (int k = 0; k < 8; k++) {
                const ulonglong2 wv = *(const ulonglong2*)(sW1p + i * 64 + h * 32 + 4 * k);
                FMA2(acc[2 * k], a, wv.x);
                FMA2(acc[2 * k + 1], a, wv.y);
            }
        }
#pragma unroll
        for (int k = 0; k < 16; k++) {
            const float2 v = unpack2(acc[k]);
            h1[h * 32 + 2 * k]     = fmaxf(v.x, 0.f);
            h1[h * 32 + 2 * k + 1] = fmaxf(v.y, 0.f);
        }
    }

    float h2[64];
#pragma unroll
    for (int q = 0; q < 4; q++) {
        ull acc[8];
#pragma unroll
        for (int k = 0; k < 4; k++) {
            const ulonglong2 bb = *(const ulonglong2*)(sb2 + q * 16 + 4 * k);
            acc[2 * k] = bb.x; acc[2 * k + 1] = bb.y;
        }
#pragma unroll
        for (int i = 0; i < 64; i++) {
            const ull a = pack2(h1[i]);
#pragma unroll
            for (int k = 0; k < 4; k++) {
                // quarters 0,1 from shared; quarters 2,3 from constant port
                const ulonglong2 wv = (q < 2)
                    ? *(const ulonglong2*)(sW2 + i * 64 + q * 16 + 4 * k)
                    : c_W2v[i * 16 + q * 4 + k];
                FMA2(acc[2 * k], a, wv.x);
                FMA2(acc[2 * k + 1], a, wv.y);
            }
        }
#pragma unroll
        for (int k = 0; k < 8; k++) {
            const float2 v = unpack2(acc[k]);
            h2[q * 16 + 2 * k]     = fmaxf(v.x, 0.f);
            h2[q * 16 + 2 * k + 1] = fmaxf(v.y, 0.f);
        }
    }

#pragma unroll
    for (int qd = 0; qd < 4; qd++) {
        ull acc[16];
#pragma unroll
        for (int k = 0; k < 8; k++) {
            const ulonglong2 bb = *(const ulonglong2*)(sb3 + qd * 32 + 4 * k);
            acc[2 * k] = bb.x; acc[2 * k + 1] = bb.y;
        }
#pragma unroll
        for (int i = 0; i < 64; i++) {
            const ull a = pack2(h2[i]);
#pragma unroll
            for (int k = 0; k < 8; k++) {
                // tiles 0,1 from shared; tiles 2,3 from constant port
                const ulonglong2 wv = (qd < 2)
                    ? *(const ulonglong2*)(sW3 + i * 128 + qd * 32 + 4 * k)
                    : c_W3v[i * 32 + qd * 8 + k];
                FMA2(acc[2 * k], a, wv.x);
                FMA2(acc[2 * k + 1], a, wv.y);
            }
        }
#pragma unroll
        for (int k = 0; k < 16; k++) {
            const float2 v = unpack2(acc[k]);
            float v0 = active ? fmaxf(v.x, 0.f) : 0.f;
            float v1 = active ? fmaxf(v.y, 0.f) : 0.f;
#pragma unroll
            for (int o = 16; o >= 4; o >>= 1) {
                v0 = fmaxf(v0, __shfl_xor_sync(0xffffffffu, v0, o));
                v1 = fmaxf(v1, __shfl_xor_sync(0xffffffffu, v1, o));
            }
            if (lane < 4) {
                atomicMax(sOutC + qd * 32 + 2 * k,     __float_as_int(v0));
                atomicMax(sOutC + qd * 32 + 2 * k + 1, __float_as_int(v1));
            }
        }
    }
    __syncthreads();

    {
        int i = tid;
        int cc = blockIdx.x * 2 + (i >> 7);
        out[(size_t)cc * 128 + (i & 127)] = __int_as_float(sOut[i]);
        i = tid + 128;
        cc = blockIdx.x * 2 + (i >> 7);
        out[(size_t)cc * 128 + (i & 127)] = __int_as_float(sOut[i]);
    }
    if (tid < 6) {
        const int cc = blockIdx.x * 2 + (tid / 3);
        out[POS_OFF + (size_t)cc * 3 + (tid % 3)] = g_centers[cc * 3 + (tid % 3)];
    }
    if (tid < 2) {
        const int cc = blockIdx.x * 2 + tid;
        out[BATCH_OFF + cc] = (float)(cc >> 11);
    }
}

// ============================================================================
extern "C" void kernel_launch(void* const* d_in, const int* in_sizes, int n_in,
                              void* d_out, int out_size) {
    const float* x   = (const float*)d_in[0];
    const float* pos = (const float*)d_in[1];
    const float* W1 = (const float*)d_in[3];
    const float* b1 = (const float*)d_in[4];
    const float* W2 = (const float*)d_in[5];
    const float* b2 = (const float*)d_in[6];
    const float* W3 = (const float*)d_in[7];
    const float* b3 = (const float*)d_in[8];
    float* out = (float*)d_out;

    // Populate constant-bank weight copies (D2D async: capture-legal, no alloc)
    cudaMemcpyToSymbolAsync(c_W2v, W2, 64 * 64 * sizeof(float), 0,
                            cudaMemcpyDeviceToDevice, 0);
    cudaMemcpyToSymbolAsync(c_W3v, W3, 64 * 128 * sizeof(float), 0,
                            cudaMemcpyDeviceToDevice, 0);

    const int fps_smem = 4 * NP * 4;   // 131072 B
    cudaFuncSetAttribute(fps_kernel, cudaFuncAttributeMaxDynamicSharedMemorySize,
                         fps_smem);
    fps_kernel<<<B_EV, FT, fps_smem>>>(pos);

    upre_kernel<<<(B_EV * NP) / 256, 256>>>(x, W1, b1);
    bq_kernel<<<NC / 8, 256>>>(pos);

    const int mlp_smem = (192 + 4096 + 8192 + 64 + 128 + 256) * 4;
    cudaFuncSetAttribute(mlp_kernel, cudaFuncAttributeMaxDynamicSharedMemorySize,
                         mlp_smem);
    mlp_kernel<<<NC / 2, 128, mlp_smem>>>(pos, W1, W2, b2, W3, b3, out);
}

// round 14
// speedup vs baseline: 1.0996x; 1.0090x over previous
#include <cuda_runtime.h>
#include <cstdint>

#define B_EV 4
#define NP 8192
#define MP 2048
#define KNN 64
#define NC (B_EV * MP)
#define R2F 0.04f
#define BIGF 1e10f
#define CAP 512

#define XLEN (NC * 128)
#define POS_OFF XLEN
#define BATCH_OFF (XLEN + NC * 3)

typedef unsigned long long ull;

__device__ float g_centers[NC * 3];
__device__ int   g_nbr[NC * KNN];
__device__ int   g_cnt[NC];
__device__ float g_U[B_EV * NP * 64];

__device__ __forceinline__ float dist2(float dx, float dy, float dz) {
    return __fadd_rn(__fadd_rn(__fmul_rn(dx, dx), __fmul_rn(dy, dy)),
                     __fmul_rn(dz, dz));
}

#define FMA2(acc, a, b) \
    asm("fma.rn.f32x2 %0, %1, %2, %0;" : "+l"(acc) : "l"(a), "l"(b))
#define ADD2(dst, a, b) \
    asm("add.rn.f32x2 %0, %1, %2;" : "=l"(dst) : "l"(a), "l"(b))
#define MUL2(dst, a, b) \
    asm("mul.rn.f32x2 %0, %1, %2;" : "=l"(dst) : "l"(a), "l"(b))

__device__ __forceinline__ ull pack2(float v) {
    ull r; asm("mov.b64 %0, {%1, %1};" : "=l"(r) : "r"(__float_as_uint(v)));
    return r;
}
__device__ __forceinline__ ull packf2(float lo, float hi) {
    ull r; asm("mov.b64 %0, {%1, %2};" : "=l"(r)
        : "r"(__float_as_uint(lo)), "r"(__float_as_uint(hi)));
    return r;
}
__device__ __forceinline__ float2 unpack2(ull p) {
    unsigned lo, hi; asm("mov.b64 {%0, %1}, %2;" : "=r"(lo), "=r"(hi) : "l"(p));
    return make_float2(__uint_as_float(lo), __uint_as_float(hi));
}

// depth-4 pairwise max tree over d[16] (replaces 16-deep sequential chain)
__device__ __forceinline__ float max16_tree(const float* d) {
    const float m0 = fmaxf(d[0], d[1]),  m1 = fmaxf(d[2], d[3]);
    const float m2 = fmaxf(d[4], d[5]),  m3 = fmaxf(d[6], d[7]);
    const float m4 = fmaxf(d[8], d[9]),  m5 = fmaxf(d[10], d[11]);
    const float m6 = fmaxf(d[12], d[13]), m7 = fmaxf(d[14], d[15]);
    const float n0 = fmaxf(m0, m1), n1 = fmaxf(m2, m3);
    const float n2 = fmaxf(m4, m5), n3 = fmaxf(m6, m7);
    return fmaxf(fmaxf(n0, n1), fmaxf(n2, n3));
}

// ============================================================================
// Kernel 1: FPS (R7-proven: 512 threads x 16 pts) + tree-max on the critical
// path. Morton counting-sort, per-thread bbox prune (sound, 1e-6 deflated),
// one barrier/iter, key-based selection (d_bits<<32 | ~orig_idx) -> max d,
// ties to lowest original index (== jnp.argmax). Exact reference rounding.
// ============================================================================
#define FT 512

__global__ __launch_bounds__(FT) void fps_kernel(const float* __restrict__ pos) {
    const int e = blockIdx.x;
    const float* pe = pos + (size_t)e * NP * 3;
    const int tid = threadIdx.x;
    const int lane = tid & 31;
    const int wid = tid >> 5;

    extern __shared__ float sm[];
    float* sx = sm;
    float* sy = sx + NP;
    float* sz = sy + NP;
    int*   sidx = (int*)(sz + NP);
    __shared__ int s_cnt[64];
    __shared__ ull s_key[2][16];

    if (tid < 64) s_cnt[tid] = 0;
    __syncthreads();

    float ox[16], oy[16], oz[16];
    int cel[16];
#pragma unroll
    for (int t = 0; t < 16; t++) {
        const int j = tid + t * FT;
        ox[t] = pe[3 * j]; oy[t] = pe[3 * j + 1]; oz[t] = pe[3 * j + 2];
        int ix = (int)(ox[t] * 4.f); ix = ix < 3 ? ix : 3;
        int iy = (int)(oy[t] * 4.f); iy = iy < 3 ? iy : 3;
        int iz = (int)(oz[t] * 4.f); iz = iz < 3 ? iz : 3;
        cel[t] = ((ix >> 1) << 5) | ((iy >> 1) << 4) | ((iz >> 1) << 3) |
                 ((ix & 1) << 2) | ((iy & 1) << 1) | (iz & 1);
        atomicAdd(&s_cnt[cel[t]], 1);
    }
    __syncthreads();
    if (tid == 0) {
        int run = 0;
        for (int c2 = 0; c2 < 64; c2++) { const int v = s_cnt[c2]; s_cnt[c2] = run; run += v; }
    }
    __syncthreads();
#pragma unroll
    for (int t = 0; t < 16; t++) {
        const int p = atomicAdd(&s_cnt[cel[t]], 1);
        sx[p] = ox[t]; sy[p] = oy[t]; sz[p] = oz[t]; sidx[p] = tid + t * FT;
    }
    __syncthreads();

    ull pxp[8], pyp[8], pzp[8];
    int io[16];
    float d[16];
    float tbnx = 2.f, tbny = 2.f, tbnz = 2.f, tbxx = -1.f, tbxy = -1.f, tbxz = -1.f;
    const int base = tid * 16;
#pragma unroll
    for (int j = 0; j < 8; j++) {
        const float ax = sx[base + 2 * j], bx = sx[base + 2 * j + 1];
        const float ay = sy[base + 2 * j], by = sy[base + 2 * j + 1];
        const float az = sz[base + 2 * j], bz = sz[base + 2 * j + 1];
        pxp[j] = packf2(ax, bx); pyp[j] = packf2(ay, by); pzp[j] = packf2(az, bz);
        io[2 * j] = sidx[base + 2 * j]; io[2 * j + 1] = sidx[base + 2 * j + 1];
        tbnx = fminf(tbnx, fminf(ax, bx)); tbxx = fmaxf(tbxx, fmaxf(ax, bx));
        tbny = fminf(tbny, fminf(ay, by)); tbxy = fmaxf(tbxy, fmaxf(ay, by));
        tbnz = fminf(tbnz, fminf(az, bz)); tbxz = fmaxf(tbxz, fmaxf(az, bz));
    }
    __syncthreads();   // sorted reads done -> repurpose buffers

    // orig-indexed position copy for O(LDS) next-center lookup
#pragma unroll
    for (int t = 0; t < 16; t++) {
        const int j = tid + t * FT;
        sx[j] = ox[t]; sy[j] = oy[t]; sz[j] = oz[t];
    }

    const float c0x = pe[0], c0y = pe[1], c0z = pe[2];
    {
        const ull ncx = pack2(-c0x), ncy = pack2(-c0y), ncz = pack2(-c0z);
#pragma unroll
        for (int j = 0; j < 8; j++) {
            ull dx, dy, dz, qx, qy, qz, s1, s2;
            ADD2(dx, pxp[j], ncx); ADD2(dy, pyp[j], ncy); ADD2(dz, pzp[j], ncz);
            MUL2(qx, dx, dx); MUL2(qy, dy, dy); MUL2(qz, dz, dz);
            ADD2(s1, qx, qy); ADD2(s2, s1, qz);
            const float2 f = unpack2(s2);
            d[2 * j] = f.x; d[2 * j + 1] = f.y;
        }
    }
    ull mykey;
    float tdmax;
    {
        const float mm = max16_tree(d);
        tdmax = mm;
        const unsigned wb = __reduce_max_sync(0xffffffffu, __float_as_uint(mm));
        unsigned cl = 0;
#pragma unroll
        for (int t = 0; t < 16; t++)
            if (__float_as_uint(d[t]) == wb) cl = max(cl, ~(unsigned)io[t]);
        const unsigned wl = __reduce_max_sync(0xffffffffu, cl);
        mykey = ((ull)wb << 32) | wl;
    }
    if (lane == 0) s_key[0][wid] = mykey;
    if (tid == 0) {
        g_centers[(e * MP) * 3 + 0] = c0x;
        g_centers[(e * MP) * 3 + 1] = c0y;
        g_centers[(e * MP) * 3 + 2] = c0z;
    }

    for (int i = 1; i < MP; i++) {
        __syncthreads();
        const ull kk = s_key[(i - 1) & 1][lane & 15];
        const unsigned hi = (unsigned)(kk >> 32);
        const unsigned lo = (unsigned)kk;
        const unsigned mhi = __reduce_max_sync(0xffffffffu, hi);
        const unsigned mlo = __reduce_max_sync(0xffffffffu, (hi == mhi) ? lo : 0u);
        const int nxt = (int)(~mlo);

        const float nx = sx[nxt], ny = sy[nxt], nz = sz[nxt];

        const float lbx = fmaxf(fmaxf(tbnx - nx, nx - tbxx), 0.f);
        const float lby = fmaxf(fmaxf(tbny - ny, ny - tbxy), 0.f);
        const float lbz = fmaxf(fmaxf(tbnz - nz, nz - tbxz), 0.f);
        const float lb2 = ((lbx * lbx + lby * lby) + lbz * lbz) * 0.999999f;
        const bool needs = (lb2 < tdmax);

        if (tid == 0) {   // store off the dependent chain
            g_centers[(e * MP + i) * 3 + 0] = nx;
            g_centers[(e * MP + i) * 3 + 1] = ny;
            g_centers[(e * MP + i) * 3 + 2] = nz;
        }

        if (__any_sync(0xffffffffu, needs)) {
            const ull ncx = pack2(-nx), ncy = pack2(-ny), ncz = pack2(-nz);
#pragma unroll
            for (int j = 0; j < 8; j++) {
                ull dx, dy, dz, qx, qy, qz, s1, s2;
                ADD2(dx, pxp[j], ncx); ADD2(dy, pyp[j], ncy); ADD2(dz, pzp[j], ncz);
                MUL2(qx, dx, dx); MUL2(qy, dy, dy); MUL2(qz, dz, dz);
                ADD2(s1, qx, qy); ADD2(s2, s1, qz);
                const float2 f = unpack2(s2);
                d[2 * j]     = fminf(d[2 * j], f.x);
                d[2 * j + 1] = fminf(d[2 * j + 1], f.y);
            }
            const float mm = max16_tree(d);
            tdmax = mm;
            const unsigned wb = __reduce_max_sync(0xffffffffu, __float_as_uint(mm));
            unsigned cl = 0;
#pragma unroll
            for (int t = 0; t < 16; t++)
                if (__float_as_uint(d[t]) == wb) cl = max(cl, ~(unsigned)io[t]);
            const unsigned wl = __reduce_max_sync(0xffffffffu, cl);
            mykey = ((ull)wb << 32) | wl;
        }
        if (lane == 0) s_key[i & 1][wid] = mykey;
    }
}

// ============================================================================
// Kernel 2: ball query + top-K (unchanged, known good)
// ============================================================================
__global__ __launch_bounds__(256) void bq_kernel(const float* __restrict__ pos) {
    __shared__ float s_d2[8][CAP];
    __shared__ int   s_idx[8][CAP];

    const int w = threadIdx.x >> 5;
    const int lane = threadIdx.x & 31;
    const int c = blockIdx.x * 8 + w;
    const int e = c >> 11;
    const float* pe = pos + (size_t)e * NP * 3;

    const float cx = g_centers[c * 3 + 0];
    const float cy = g_centers[c * 3 + 1];
    const float cz = g_centers[c * 3 + 2];

    int cnt = 0;
    const unsigned lmask = (1u << lane) - 1u;
    for (int j = lane; j < NP; j += 32) {
        const float d2v = dist2(pe[3 * j] - cx, pe[3 * j + 1] - cy, pe[3 * j + 2] - cz);
        const bool inr = (d2v <= R2F);
        const unsigned mball = __ballot_sync(0xffffffffu, inr);
        if (inr) {
            const int slot = cnt + __popc(mball & lmask);
            if (slot < CAP) { s_d2[w][slot] = d2v; s_idx[w][slot] = j; }
        }
        cnt += __popc(mball);
    }
    const int C = (cnt < CAP) ? cnt : CAP;

    if (C <= KNN) {
        for (int k = lane; k < KNN; k += 32)
            g_nbr[c * KNN + k] = (k < C) ? s_idx[w][k] : 0;
        if (lane == 0) g_cnt[c] = C;
    } else {
        for (int s = 0; s < KNN; s++) {
            ull best = ~0ull;
            for (int t = lane; t < C; t += 32) {
                const ull key = ((ull)__float_as_uint(s_d2[w][t]) << 32) | (unsigned)t;
                best = (key < best) ? key : best;
            }
#pragma unroll
            for (int o = 16; o > 0; o >>= 1) {
                const ull other = __shfl_down_sync(0xffffffffu, best, o);
                best = (other < best) ? other : best;
            }
            best = __shfl_sync(0xffffffffu, best, 0);
            const int slot = (int)(unsigned)best;
            if (lane == 0) {
                g_nbr[c * KNN + s] = s_idx[w][slot];
                s_d2[w][slot] = BIGF;
            }
            __syncwarp();
        }
        if (lane == 0) g_cnt[c] = KNN;
    }
}

// ============================================================================
// Kernel 0b: U = b1 + x @ W1[0:32]  (unchanged, known good)
// ============================================================================
__global__ __launch_bounds__(256) void upre_kernel(
    const float* __restrict__ x, const float* __restrict__ W1,
    const float* __restrict__ b1)
{
    __shared__ float sW[32 * 64];
    __shared__ float sb[64];
    const int tid = threadIdx.x;
    for (int i = tid; i < 2048; i += 256) sW[i] = W1[i];
    if (tid < 64) sb[tid] = b1[tid];
    __syncthreads();

    const int row = blockIdx.x * 256 + tid;
    float inv[32];
    const float4* xr = (const float4*)(x + (size_t)row * 32);
#pragma unroll
    for (int q = 0; q < 8; q++) {
        const float4 v = xr[q];
        inv[4 * q] = v.x; inv[4 * q + 1] = v.y; inv[4 * q + 2] = v.z; inv[4 * q + 3] = v.w;
    }
    float4* ur = (float4*)(g_U + (size_t)row * 64);
#pragma unroll
    for (int h = 0; h < 2; h++) {
        ull acc[16];
#pragma unroll
        for (int k = 0; k < 8; k++) {
            const ulonglong2 bb = *(const ulonglong2*)(sb + h * 32 + 4 * k);
            acc[2 * k] = bb.x; acc[2 * k + 1] = bb.y;
        }
#pragma unroll
        for (int i = 0; i < 32; i++) {
            const ull a = pack2(inv[i]);
#pragma unroll
            for (int k = 0; k < 8; k++) {
                const ulonglong2 wv = *(const ulonglong2*)(sW + i * 64 + h * 32 + 4 * k);
                FMA2(acc[2 * k], a, wv.x);
                FMA2(acc[2 * k + 1], a, wv.y);
            }
        }
#pragma unroll
        for (int k = 0; k < 8; k++) {
            const float2 v0 = unpack2(acc[2 * k]);
            const float2 v1 = unpack2(acc[2 * k + 1]);
            ur[h * 8 + k] = make_float4(v0.x, v0.y, v1.x, v1.y);
        }
    }
}

// ============================================================================
// Kernel 3: gather + MLP + max-pool (R5-proven, pure shared weights)
// ============================================================================
__global__ __launch_bounds__(128, 3) void mlp_kernel(
    const float* __restrict__ pos,
    const float* __restrict__ W1,
    const float* __restrict__ W2, const float* __restrict__ b2,
    const float* __restrict__ W3, const float* __restrict__ b3,
    float* __restrict__ out)
{
    extern __shared__ float smem[];
    float* sW1p = smem;            // 192
    float* sW2 = sW1p + 192;       // 4096
    float* sW3 = sW2 + 4096;       // 8192
    float* sb2 = sW3 + 8192;       // 64
    float* sb3 = sb2 + 64;         // 128
    int*   sOut = (int*)(sb3 + 128);

    const int tid = threadIdx.x;
    for (int i = tid; i < 192; i += 128) sW1p[i] = W1[2048 + i];
    for (int i = tid; i < 4096; i += 128) sW2[i] = W2[i];
    for (int i = tid; i < 8192; i += 128) sW3[i] = W3[i];
    if (tid < 64) sb2[tid] = b2[tid];
    sb3[tid] = b3[tid];
    sOut[tid] = 0;
    sOut[tid + 128] = 0;
    __syncthreads();

    const int cl = tid >> 6;
    const int n  = tid & 63;
    const int lane = tid & 31;
    const int c  = blockIdx.x * 2 + cl;
    const int e  = c >> 11;
    const bool active = (n < g_cnt[c]);
    int* sOutC = sOut + cl * 128;

    const int idx = g_nbr[c * KNN + n];
    const int row = e * NP + idx;

    float rel[3];
    rel[0] = pos[row * 3 + 0] - g_centers[c * 3 + 0];
    rel[1] = pos[row * 3 + 1] - g_centers[c * 3 + 1];
    rel[2] = pos[row * 3 + 2] - g_centers[c * 3 + 2];

    float h1[64];
    const float4* ur = (const float4*)(g_U + (size_t)row * 64);
#pragma unroll
    for (int h = 0; h < 2; h++) {
        ull acc[16];
#pragma unroll
        for (int q = 0; q < 8; q++) {
            const float4 u = ur[h * 8 + q];
            acc[2 * q]     = packf2(u.x, u.y);
            acc[2 * q + 1] = packf2(u.z, u.w);
        }
#pragma unroll
        for (int i = 0; i < 3; i++) {
            const ull a = pack2(rel[i]);
#pragma unroll
            for (int k = 0; k < 8; k++) {
                const ulonglong2 wv = *(const ulonglong2*)(sW1p + i * 64 + h * 32 + 4 * k);
                FMA2(acc[2 * k], a, wv.x);
                FMA2(acc[2 * k + 1], a, wv.y);
            }
        }
#pragma unroll
        for (int k = 0; k < 16; k++) {
            const float2 v = unpack2(acc[k]);
            h1[h * 32 + 2 * k]     = fmaxf(v.x, 0.f);
            h1[h * 32 + 2 * k + 1] = fmaxf(v.y, 0.f);
        }
    }

    float h2[64];
#pragma unroll
    for (int q = 0; q < 4; q++) {
        ull acc[8];
#pragma unroll
        for (int k = 0; k < 4; k++) {
            const ulonglong2 bb = *(const ulonglong2*)(sb2 + q * 16 + 4 * k);
            acc[2 * k] = bb.x; acc[2 * k + 1] = bb.y;
        }
#pragma unroll
        for (int i = 0; i < 64; i++) {
            const ull a = pack2(h1[i]);
#pragma unroll
            for (int k = 0; k < 4; k++) {
                const ulonglong2 wv = *(const ulonglong2*)(sW2 + i * 64 + q * 16 + 4 * k);
                FMA2(acc[2 * k], a, wv.x);
                FMA2(acc[2 * k + 1], a, wv.y);
            }
        }
#pragma unroll
        for (int k = 0; k < 8; k++) {
            const float2 v = unpack2(acc[k]);
            h2[q * 16 + 2 * k]     = fmaxf(v.x, 0.f);
            h2[q * 16 + 2 * k + 1] = fmaxf(v.y, 0.f);
        }
    }

#pragma unroll
    for (int qd = 0; qd < 4; qd++) {
        ull acc[16];
#pragma unroll
        for (int k = 0; k < 8; k++) {
            const ulonglong2 bb = *(const ulonglong2*)(sb3 + qd * 32 + 4 * k);
            acc[2 * k] = bb.x; acc[2 * k + 1] = bb.y;
        }
#pragma unroll
        for (int i = 0; i < 64; i++) {
            const ull a = pack2(h2[i]);
#pragma unroll
            for (int k = 0; k < 8; k++) {
                const ulonglong2 wv = *(const ulonglong2*)(sW3 + i * 128 + qd * 32 + 4 * k);
                FMA2(acc[2 * k], a, wv.x);
                FMA2(acc[2 * k + 1], a, wv.y);
            }
        }
#pragma unroll
        for (int k = 0; k < 16; k++) {
            const float2 v = unpack2(acc[k]);
            float v0 = active ? fmaxf(v.x, 0.f) : 0.f;
            float v1 = active ? fmaxf(v.y, 0.f) : 0.f;
#pragma unroll
            for (int o = 16; o >= 4; o >>= 1) {
                v0 = fmaxf(v0, __shfl_xor_sync(0xffffffffu, v0, o));
                v1 = fmaxf(v1, __shfl_xor_sync(0xffffffffu, v1, o));
            }
            if (lane < 4) {
                atomicMax(sOutC + qd * 32 + 2 * k,     __float_as_int(v0));
                atomicMax(sOutC + qd * 32 + 2 * k + 1, __float_as_int(v1));
            }
        }
    }
    __syncthreads();

    {
        int i = tid;
        int cc = blockIdx.x * 2 + (i >> 7);
        out[(size_t)cc * 128 + (i & 127)] = __int_as_float(sOut[i]);
        i = tid + 128;
        cc = blockIdx.x * 2 + (i >> 7);
        out[(size_t)cc * 128 + (i & 127)] = __int_as_float(sOut[i]);
    }
    if (tid < 6) {
        const int cc = blockIdx.x * 2 + (tid / 3);
        out[POS_OFF + (size_t)cc * 3 + (tid % 3)] = g_centers[cc * 3 + (tid % 3)];
    }
    if (tid < 2) {
        const int cc = blockIdx.x * 2 + tid;
        out[BATCH_OFF + cc] = (float)(cc >> 11);
    }
}

// ============================================================================
extern "C" void kernel_launch(void* const* d_in, const int* in_sizes, int n_in,
                              void* d_out, int out_size) {
    const float* x   = (const float*)d_in[0];
    const float* pos = (const float*)d_in[1];
    const float* W1 = (const float*)d_in[3];
    const float* b1 = (const float*)d_in[4];
    const float* W2 = (const float*)d_in[5];
    const float* b2 = (const float*)d_in[6];
    const float* W3 = (const float*)d_in[7];
    const float* b3 = (const float*)d_in[8];
    float* out = (float*)d_out;

    const int fps_smem = 4 * NP * 4;   // 131072 B
    cudaFuncSetAttribute(fps_kernel, cudaFuncAttributeMaxDynamicSharedMemorySize,
                         fps_smem);
    fps_kernel<<<B_EV, FT, fps_smem>>>(pos);

    upre_kernel<<<(B_EV * NP) / 256, 256>>>(x, W1, b1);
    bq_kernel<<<NC / 8, 256>>>(pos);

    const int mlp_smem = (192 + 4096 + 8192 + 64 + 128 + 256) * 4;
    cudaFuncSetAttribute(mlp_kernel, cudaFuncAttributeMaxDynamicSharedMemorySize,
                         mlp_smem);
    mlp_kernel<<<NC / 2, 128, mlp_smem>>>(pos, W1, W2, b2, W3, b3, out);
}